// round 16
// baseline (speedup 1.0000x reference)
#include <cuda_runtime.h>
#include <cuda_bf16.h>
#include <math.h>
#include <stdint.h>

#define B_  64
#define Q_  1000
#define BQ  64000
#define D_  256
#define LOGIT_THR 0.8472978603872034f   // sigmoid(x)>0.7  <=>  x>ln(7/3)

// Weights: single linear array, sel = (plane<<2)|L, 65536 elems each
__device__ __nv_bfloat16 g_w[8 * D_ * D_];
__device__ int           g_idx[BQ];     // q | (cand_bits<<16)
__device__ int           g_cnt;

__device__ __forceinline__ uint32_t smem_u32(const void* p) {
    uint32_t r;
    asm("{ .reg .u64 t; cvta.to.shared.u64 t, %1; cvt.u32.u64 %0, t; }" : "=r"(r) : "l"(p));
    return r;
}
__device__ __forceinline__ void cp16(uint32_t dst, const void* src) {
    asm volatile("cp.async.cg.shared.global [%0], [%1], 16;" :: "r"(dst), "l"(src));
}
#define CP_COMMIT()  asm volatile("cp.async.commit_group;")
#define CP_WAIT1()   asm volatile("cp.async.wait_group 1;")
#define CP_WAIT0()   asm volatile("cp.async.wait_group 0;")

#define LDSM4(r, addr) \
    asm volatile("ldmatrix.sync.aligned.m8n8.x4.shared.b16 {%0,%1,%2,%3}, [%4];" \
        : "=r"((r)[0]), "=r"((r)[1]), "=r"((r)[2]), "=r"((r)[3]) : "r"(addr))

#define MMA(d, a, b0, b1) \
    asm volatile("mma.sync.aligned.m16n8k16.row.col.f32.bf16.bf16.f32 " \
        "{%0,%1,%2,%3},{%4,%5,%6,%7},{%8,%9},{%0,%1,%2,%3};" \
        : "+f"((d)[0]), "+f"((d)[1]), "+f"((d)[2]), "+f"((d)[3]) \
        : "r"((a)[0]), "r"((a)[1]), "r"((a)[2]), "r"((a)[3]), "r"(b0), "r"(b1))

__device__ __forceinline__ uint32_t pack2(float a, float b) {
    return (uint32_t)__bfloat16_as_ushort(__float2bfloat16(a))
         | ((uint32_t)__bfloat16_as_ushort(__float2bfloat16(b)) << 16);
}
__device__ __forceinline__ void split2(float a, float b, uint32_t& hw, uint32_t& lw) {
    __nv_bfloat16 h0 = __float2bfloat16(a), h1 = __float2bfloat16(b);
    hw = (uint32_t)__bfloat16_as_ushort(h0) | ((uint32_t)__bfloat16_as_ushort(h1) << 16);
    lw = pack2(a - __bfloat162float(h0), b - __bfloat162float(h1));
}

// ---------------------------------------------------------------------------
// k_prep: counters + weight split + output zero
// ---------------------------------------------------------------------------
__global__ void k_prep(const float* __restrict__ W0, const float* __restrict__ W1,
                       const float* __restrict__ W2, const float* __restrict__ W3,
                       float* __restrict__ out, int out_size)
{
    int bid = blockIdx.x, tid = threadIdx.x;
    if (bid == 0 && tid == 0) g_cnt = 0;
    if (bid < 1024) {
        int wSel = bid >> 8;
        int idx = ((bid & 255) << 8) | tid;
        const float* W = (wSel == 0) ? W0 : (wSel == 1) ? W1 : (wSel == 2) ? W2 : W3;
        int k = idx >> 8, n = idx & 255;
        float x = W[idx];
        __nv_bfloat16 h = __float2bfloat16(x);
        g_w[((size_t)wSel << 16) + n * D_ + k] = h;
        g_w[((size_t)(4 + wSel) << 16) + n * D_ + k] =
            __float2bfloat16(x - __bfloat162float(h));
    } else {
        int i = (bid - 1024) * 256 + tid;
        int zn4 = ((out_size >= BQ * 10 + BQ * 2) ? (BQ * 10 + BQ * 2) : (BQ * 10)) / 4;
        if (i < zn4) ((float4*)out)[i] = make_float4(0.f, 0.f, 0.f, 0.f);
    }
}

// ---------------------------------------------------------------------------
// k_mask (unchanged)
// ---------------------------------------------------------------------------
__global__ void __launch_bounds__(1024) k_mask(const float* __restrict__ logits,
                                               const float* __restrict__ boxes)
{
    __shared__ float tx1[Q_], ty1[Q_], tx2[Q_], ty2[Q_], tar[Q_];
    __shared__ unsigned char tfl[Q_];
    __shared__ int s_fq[512];
    __shared__ int tn, fn;

    int b = blockIdx.x >> 1, slice = blockIdx.x & 1;
    int t = threadIdx.x;
    if (t == 0) { tn = 0; fn = 0; }
    __syncthreads();

    if (t < Q_) {
        const float* l = logits + ((long)b * Q_ + t) * 6;
        unsigned f = 0;
        if (l[0] > LOGIT_THR) f |= 1u;
        if (l[4] > LOGIT_THR) f |= 2u;
        if (l[1] > LOGIT_THR) f |= 4u;
        if (l[5] > LOGIT_THR) f |= 8u;
        if (f) {
            const float* bx = boxes + ((long)b * Q_ + t) * 4;
            float cx = bx[0], cy = bx[1], w = bx[2], h = bx[3];
            if (f & 0xCu) {
                int p = atomicAdd(&tn, 1);
                tx1[p] = cx - 0.5f * w; ty1[p] = cy - 0.5f * h;
                tx2[p] = cx + 0.5f * w; ty2[p] = cy + 0.5f * h;
                tar[p] = w * h;
                tfl[p] = (unsigned char)((f >> 2) & 3u);
            }
            if ((f & 3u) && ((t >> 9) == slice)) {
                int p = atomicAdd(&fn, 1);
                s_fq[p] = t | (int)((f & 3u) << 16);
            }
        }
    }
    __syncthreads();

    int nt = tn, nf = fn;
    int sub = t & 3;

    for (int e = t >> 2; e < nf; e += 256) {
        int v = s_fq[e];
        int q = v & 0xFFFF;
        unsigned need = (unsigned)(v >> 16) & 3u;
        const float4 bx = *(const float4*)(boxes + ((long)b * Q_ + q) * 4);
        float x1 = bx.x - 0.5f * bx.z, y1 = bx.y - 0.5f * bx.w;
        float x2 = bx.x + 0.5f * bx.z, y2 = bx.y + 0.5f * bx.w;
        float ar = bx.z * bx.w;
        unsigned has = 0;
        for (int j = sub; j < nt; j += 4) {
            float xl = fmaxf(x1, tx1[j]), yt = fmaxf(y1, ty1[j]);
            float xr = fminf(x2, tx2[j]), yb = fminf(y2, ty2[j]);
            float inter = fmaxf(xr - xl, 0.f) * fmaxf(yb - yt, 0.f);
            float uni = ar + tar[j] - inter;
            if (inter > 0.5f * uni) {
                has |= (unsigned)tfl[j];
                if ((has & need) == need) break;
            }
        }
        has |= __shfl_xor_sync(0xffffffffu, has, 1);
        has |= __shfl_xor_sync(0xffffffffu, has, 2);
        if (sub == 0) {
            unsigned cm = need & ~has;
            if (cm) {
                int pos = atomicAdd(&g_cnt, 1);
                g_idx[pos] = (b * Q_ + q) | ((int)cm << 16);
            }
        }
    }
}

// ---------------------------------------------------------------------------
// k_fused: 64-row tiles, occ 2, 2 B buffers, 64 stages, hoisted addressing.
// smem map:
//   ACT_H 0..32768 | ACT_L 32768..65536 (4 K-blocks of 8KB each, per plane)
//   B 65536..98304 (2 x 16KB)
//   B4A 98304 (4KB) | LNG 102400 | LNB 103424 | WS 104448 | WB3 105472 (4KB)
//   PS 109568 (1KB) | PS2 110592 (1KB) | DP overlays 109568 (4KB, L3 only)
//   SC 113664 (256B) | QI 113920 (256B)  => 114176 total (occ 2)
// ---------------------------------------------------------------------------
#define S_ACTH 0
#define S_ACTL 32768
#define S_B    65536
#define S_B4A  98304
#define S_LNG  102400
#define S_LNB  103424
#define S_WS   104448
#define S_WB3  105472
#define S_PS   109568
#define S_PS2  110592
#define S_DP   109568
#define S_SC   113664
#define S_QI   113920
#define FUSED_SMEM 114176

__global__ void __launch_bounds__(256, 2) k_fused(
    const float* __restrict__ feat, const float* __restrict__ boxes,
    const float* __restrict__ b1, const float* __restrict__ lng, const float* __restrict__ lnb,
    const float* __restrict__ b2, const float* __restrict__ ws, const float* __restrict__ bs,
    const float* __restrict__ b3, const float* __restrict__ b4,
    const float* __restrict__ wb3, const float* __restrict__ bb3,
    float* __restrict__ out, int out_size)
{
    int cnt = g_cnt;
    int blockRow = blockIdx.x * 64;
    if (blockRow >= cnt) return;

    extern __shared__ __align__(1024) char sm[];
    uint32_t base = smem_u32(sm);
    int tid = threadIdx.x, wid = tid >> 5, lane = tid & 31;
    int wm = wid & 1, wn = wid >> 1;            // warp tile 32M x 64N
    int qg = lane >> 2, qt = lane & 3;

    // hoisted cp.async addressing
    int n0 = tid >> 2, sg = tid & 3;
    uint32_t sdst0 = base + S_B + n0 * 64 + ((sg * 16) ^ ((n0 & 6) << 3));
    uint32_t goff0 = (uint32_t)n0 * D_ + sg * 8;

    // hoisted ldmatrix addressing
    int rl = lane & 15;
    int cb0 = (lane >> 4) << 4;
    uint32_t swr = (uint32_t)((rl & 7) << 4);
    uint32_t offA[2][2];                        // [K-32 half of block][ks]
#pragma unroll
    for (int h = 0; h < 2; h++)
#pragma unroll
        for (int k = 0; k < 2; k++)
            offA[h][k] = ((uint32_t)(h * 64 + cb0 + k * 32)) ^ swr;
    uint32_t aBase[2];
#pragma unroll
    for (int i = 0; i < 2; i++)
        aBase[i] = (uint32_t)((wm * 32 + i * 16 + rl) * 128);
    uint32_t bBase[4];
#pragma unroll
    for (int j4 = 0; j4 < 4; j4++)
        bBase[j4] = (uint32_t)((wn * 64 + j4 * 16 + rl) * 64);
    uint32_t boff[2];
#pragma unroll
    for (int k = 0; k < 2; k++)
        boff[k] = ((uint32_t)(cb0 + k * 32)) ^ ((uint32_t)((rl & 6) << 3));

    // per-CTA prologue: qidx + gather + aux
    if (tid < 64) {
        int gr = blockRow + tid;
        ((int*)(sm + S_QI))[tid] = (gr < cnt) ? g_idx[gr] : -1;
    }
    for (int it = tid; it < 2048; it += 256) {   // 64 rows x 32 groups
        int row = it >> 5, grp = it & 31;
        uint4 hi = make_uint4(0, 0, 0, 0), lo = make_uint4(0, 0, 0, 0);
        int gr = blockRow + row;
        if (gr < cnt) {
            int q = g_idx[gr] & 0xFFFF;
            const float4* f4 = (const float4*)feat + (size_t)q * 64 + grp * 2;
            float4 fa = __ldg(f4), fb = __ldg(f4 + 1);
            split2(fa.x, fa.y, hi.x, lo.x);
            split2(fa.z, fa.w, hi.y, lo.y);
            split2(fb.x, fb.y, hi.z, lo.z);
            split2(fb.z, fb.w, hi.w, lo.w);
        }
        int c8 = grp * 8;
        int blk = c8 >> 6;
        uint32_t sw = blk * 8192 + row * 128 + (((c8 & 63) * 2) ^ ((row & 7) << 4));
        *(uint4*)(sm + S_ACTH + sw) = hi;
        *(uint4*)(sm + S_ACTL + sw) = lo;
    }
    {
        float* s_b4 = (float*)(sm + S_B4A);
        s_b4[0 * 256 + tid] = __ldg(b1 + tid);
        s_b4[1 * 256 + tid] = __ldg(b2 + tid);
        s_b4[2 * 256 + tid] = __ldg(b3 + tid);
        s_b4[3 * 256 + tid] = __ldg(b4 + tid);
        ((float*)(sm + S_LNG))[tid] = __ldg(lng + tid);
        ((float*)(sm + S_LNB))[tid] = __ldg(lnb + tid);
        ((float*)(sm + S_WS))[tid]  = __ldg(ws + tid);
        ((float4*)(sm + S_WB3))[tid] = __ldg((const float4*)wb3 + tid);
    }
    // pre-issue stage 0 (L=0, hi plane, c2=0)
    {
        const __nv_bfloat16* w = g_w + goff0;
        cp16(sdst0, w); cp16(sdst0 + 4096, w + 16384);
        cp16(sdst0 + 8192, w + 32768); cp16(sdst0 + 12288, w + 49152);
        CP_COMMIT();
    }
    __syncthreads();

    float* s_ps  = (float*)(sm + S_PS);
    float* s_ps2 = (float*)(sm + S_PS2);
    float* s_dp  = (float*)(sm + S_DP);
    float* s_sc  = (float*)(sm + S_SC);

    float acc[2][8][4];
    float mu[2][2], rs[2][2], scp[2][2];

#pragma unroll 1
    for (int t = 0; t < 64; t++) {
        int L = t >> 4, rem = t & 15, c2 = rem >> 1, plane = rem & 1;

        // issue stage t+1 (prev-iter end sync protects buf (t+1)&1)
        {
            int t1 = t + 1;
            if (t1 < 64) {
                int sel = ((t1 & 1) << 2) | (t1 >> 4);
                const __nv_bfloat16* w = g_w + ((size_t)sel << 16)
                                       + (((t1 & 15) >> 1) * 32) + goff0;
                uint32_t dst = sdst0 + ((uint32_t)(t1 & 1) << 14);
                cp16(dst, w); cp16(dst + 4096, w + 16384);
                cp16(dst + 8192, w + 32768); cp16(dst + 12288, w + 49152);
            }
            CP_COMMIT();
        }
        CP_WAIT1();                  // group t complete
        __syncthreads();

        if (rem == 0) {
#pragma unroll
            for (int i = 0; i < 2; i++)
#pragma unroll
                for (int j = 0; j < 8; j++)
#pragma unroll
                    for (int r = 0; r < 4; r++) acc[i][j][r] = 0.f;
        }

        uint32_t bufb = base + S_B + ((uint32_t)(t & 1) << 14);
        uint32_t ab = base + S_ACTH + ((uint32_t)(c2 >> 1) << 13);
        int half = c2 & 1;
#pragma unroll
        for (int ks = 0; ks < 2; ks++) {
            uint32_t Bf[4][4], Af[2][4];
            LDSM4(Bf[0], bufb + bBase[0] + boff[ks]);
            LDSM4(Bf[1], bufb + bBase[1] + boff[ks]);
            LDSM4(Bf[2], bufb + bBase[2] + boff[ks]);
            LDSM4(Bf[3], bufb + bBase[3] + boff[ks]);
            LDSM4(Af[0], ab + aBase[0] + offA[half][ks]);
            LDSM4(Af[1], ab + aBase[1] + offA[half][ks]);
#pragma unroll
            for (int i = 0; i < 2; i++)
#pragma unroll
                for (int j = 0; j < 8; j++) {
                    int j4 = j >> 1, sel = j & 1;
                    MMA(acc[i][j], Af[i], Bf[j4][sel], Bf[j4][sel + 2]);
                }
            if (plane == 0) {
                LDSM4(Af[0], ab + 32768 + aBase[0] + offA[half][ks]);
                LDSM4(Af[1], ab + 32768 + aBase[1] + offA[half][ks]);
#pragma unroll
                for (int i = 0; i < 2; i++)
#pragma unroll
                    for (int j = 0; j < 8; j++) {
                        int j4 = j >> 1, sel = j & 1;
                        MMA(acc[i][j], Af[i], Bf[j4][sel], Bf[j4][sel + 2]);
                    }
            }
        }

        // epilogue at layer end
        if (rem == 15) {
            const float* s_bias = (const float*)(sm + S_B4A) + L * 256;
            if (L == 0) {
                const float* g1 = (const float*)(sm + S_LNG);
                const float* g2 = (const float*)(sm + S_LNB);
                float ps[2][2] = {{0,0},{0,0}}, ps2[2][2] = {{0,0},{0,0}};
#pragma unroll
                for (int i = 0; i < 2; i++)
#pragma unroll
                    for (int j = 0; j < 8; j++) {
                        int c0 = wn * 64 + j * 8 + 2 * qt;
                        float v00 = acc[i][j][0] + s_bias[c0], v01 = acc[i][j][1] + s_bias[c0 + 1];
                        float v10 = acc[i][j][2] + s_bias[c0], v11 = acc[i][j][3] + s_bias[c0 + 1];
                        ps[i][0] += v00 + v01; ps2[i][0] += v00 * v00 + v01 * v01;
                        ps[i][1] += v10 + v11; ps2[i][1] += v10 * v10 + v11 * v11;
                    }
#pragma unroll
                for (int i = 0; i < 2; i++)
#pragma unroll
                    for (int h = 0; h < 2; h++) {
                        ps[i][h]  += __shfl_xor_sync(0xffffffffu, ps[i][h], 1);
                        ps[i][h]  += __shfl_xor_sync(0xffffffffu, ps[i][h], 2);
                        ps2[i][h] += __shfl_xor_sync(0xffffffffu, ps2[i][h], 1);
                        ps2[i][h] += __shfl_xor_sync(0xffffffffu, ps2[i][h], 2);
                        if (qt == 0) {
                            int r = wm * 32 + i * 16 + qg + h * 8;
                            s_ps[r * 4 + wn] = ps[i][h];
                            s_ps2[r * 4 + wn] = ps2[i][h];
                        }
                    }
                __syncthreads();
#pragma unroll
                for (int i = 0; i < 2; i++)
#pragma unroll
                    for (int h = 0; h < 2; h++) {
                        int r = wm * 32 + i * 16 + qg + h * 8;
                        float S = s_ps[r * 4] + s_ps[r * 4 + 1] + s_ps[r * 4 + 2] + s_ps[r * 4 + 3];
                        float S2 = s_ps2[r * 4] + s_ps2[r * 4 + 1] + s_ps2[r * 4 + 2] + s_ps2[r * 4 + 3];
                        float m = S * (1.f / 256.f);
                        mu[i][h] = m;
                        rs[i][h] = rsqrtf(S2 * (1.f / 256.f) - m * m + 1e-5f);
                    }
#pragma unroll
                for (int i = 0; i < 2; i++)
#pragma unroll
                    for (int j = 0; j < 8; j++) {
                        int c0 = wn * 64 + j * 8 + 2 * qt;
                        int byte = (c0 & 63) * 2, blk = c0 >> 6;
#pragma unroll
                        for (int h = 0; h < 2; h++) {
                            int r = wm * 32 + i * 16 + qg + h * 8;
                            float v0 = fmaxf(((acc[i][j][2 * h]     + s_bias[c0])     - mu[i][h]) * rs[i][h] * g1[c0]     + g2[c0],     0.f);
                            float v1 = fmaxf(((acc[i][j][2 * h + 1] + s_bias[c0 + 1]) - mu[i][h]) * rs[i][h] * g1[c0 + 1] + g2[c0 + 1], 0.f);
                            uint32_t hw, lw; split2(v0, v1, hw, lw);
                            uint32_t a = blk * 8192 + r * 128 + ((byte & ~15) ^ ((r & 7) << 4)) + (byte & 15);
                            *(uint32_t*)(sm + S_ACTH + a) = hw;
                            *(uint32_t*)(sm + S_ACTL + a) = lw;
                        }
                    }
            } else if (L == 1) {
                const float* wsv = (const float*)(sm + S_WS);
                scp[0][0] = scp[0][1] = scp[1][0] = scp[1][1] = 0.f;
#pragma unroll
                for (int i = 0; i < 2; i++)
#pragma unroll
                    for (int j = 0; j < 8; j++) {
                        int c0 = wn * 64 + j * 8 + 2 * qt;
                        int byte = (c0 & 63) * 2, blk = c0 >> 6;
#pragma unroll
                        for (int h = 0; h < 2; h++) {
                            int r = wm * 32 + i * 16 + qg + h * 8;
                            float v0 = acc[i][j][2 * h]     + s_bias[c0];
                            float v1 = acc[i][j][2 * h + 1] + s_bias[c0 + 1];
                            scp[i][h] += v0 * wsv[c0] + v1 * wsv[c0 + 1];
                            uint32_t hw, lw; split2(v0, v1, hw, lw);
                            uint32_t a = blk * 8192 + r * 128 + ((byte & ~15) ^ ((r & 7) << 4)) + (byte & 15);
                            *(uint32_t*)(sm + S_ACTH + a) = hw;
                            *(uint32_t*)(sm + S_ACTL + a) = lw;
                        }
                    }
#pragma unroll
                for (int i = 0; i < 2; i++)
#pragma unroll
                    for (int h = 0; h < 2; h++) {
                        scp[i][h] += __shfl_xor_sync(0xffffffffu, scp[i][h], 1);
                        scp[i][h] += __shfl_xor_sync(0xffffffffu, scp[i][h], 2);
                        if (qt == 0) {
                            int r = wm * 32 + i * 16 + qg + h * 8;
                            s_ps[r * 4 + wn] = scp[i][h];
                        }
                    }
                __syncthreads();
                if (tid < 64)
                    s_sc[tid] = s_ps[tid * 4] + s_ps[tid * 4 + 1]
                              + s_ps[tid * 4 + 2] + s_ps[tid * 4 + 3] + __ldg(bs);
            } else if (L == 2) {
#pragma unroll
                for (int i = 0; i < 2; i++)
#pragma unroll
                    for (int j = 0; j < 8; j++) {
                        int c0 = wn * 64 + j * 8 + 2 * qt;
                        int byte = (c0 & 63) * 2, blk = c0 >> 6;
#pragma unroll
                        for (int h = 0; h < 2; h++) {
                            int r = wm * 32 + i * 16 + qg + h * 8;
                            float v0 = fmaxf(acc[i][j][2 * h]     + s_bias[c0],     0.f);
                            float v1 = fmaxf(acc[i][j][2 * h + 1] + s_bias[c0 + 1], 0.f);
                            uint32_t hw, lw; split2(v0, v1, hw, lw);
                            uint32_t a = blk * 8192 + r * 128 + ((byte & ~15) ^ ((r & 7) << 4)) + (byte & 15);
                            *(uint32_t*)(sm + S_ACTH + a) = hw;
                            *(uint32_t*)(sm + S_ACTL + a) = lw;
                        }
                    }
            } else {
                const float* w3t = (const float*)(sm + S_WB3);
#pragma unroll
                for (int i = 0; i < 2; i++) {
                    float dp[2][4] = {{0,0,0,0},{0,0,0,0}};
#pragma unroll
                    for (int j = 0; j < 8; j++) {
                        int c0 = wn * 64 + j * 8 + 2 * qt;
#pragma unroll
                        for (int h = 0; h < 2; h++) {
                            float v0 = fmaxf(acc[i][j][2 * h]     + s_bias[c0],     0.f);
                            float vv = fmaxf(acc[i][j][2 * h + 1] + s_bias[c0 + 1], 0.f);
                            const float* w0 = &w3t[c0 * 4];
#pragma unroll
                            for (int k = 0; k < 4; k++)
                                dp[h][k] += v0 * w0[k] + vv * w0[4 + k];
                        }
                    }
#pragma unroll
                    for (int h = 0; h < 2; h++)
#pragma unroll
                        for (int k = 0; k < 4; k++) {
                            dp[h][k] += __shfl_xor_sync(0xffffffffu, dp[h][k], 1);
                            dp[h][k] += __shfl_xor_sync(0xffffffffu, dp[h][k], 2);
                            if (qt == 0) {
                                int r = wm * 32 + i * 16 + qg + h * 8;
                                s_dp[r * 16 + wn * 4 + k] = dp[h][k];
                            }
                        }
                }
                __syncthreads();
                if (tid < 64) {
                    int v = ((int*)(sm + S_QI))[tid];
                    if (v >= 0) {
                        float d[4];
#pragma unroll
                        for (int k = 0; k < 4; k++)
                            d[k] = s_dp[tid * 16 + k] + s_dp[tid * 16 + 4 + k]
                                 + s_dp[tid * 16 + 8 + k] + s_dp[tid * 16 + 12 + k]
                                 + __ldg(bb3 + k);
                        float scv = s_sc[tid];
                        int q = v & 0xFFFF;
                        unsigned cm = (unsigned)(v >> 16);
                        float4 bx = *(const float4*)(boxes + (long)q * 4);
                        float cx = bx.x, cy = bx.y, w = bx.z, hh = bx.w;
                        float ny = cy + 0.5f * hh, nw = w * 0.8f, nh = hh * 0.8f;
                        float lb[4]  = {cx,            ny, nw, nh};
                        float rbx[4] = {cx + 0.1f * w, ny, nw, nh};
#pragma unroll
                        for (int s = 0; s < 2; s++) {
                            if (!((cm >> s) & 1u)) continue;
                            const float* cb = s ? rbx : lb;
                            long basei = ((long)q * 2 + s) * 5;
#pragma unroll
                            for (int c = 0; c < 4; c++) {
                                float x = fminf(fmaxf(cb[c], 0.f), 1.f);
                                float inv = logf(fmaxf(x, 1e-5f) / fmaxf(1.f - x, 1e-5f));
                                out[basei + c] = 1.f / (1.f + expf(-(d[c] + inv)));
                            }
                            out[basei + 4] = scv;
                            if (out_size >= BQ * 10 + BQ * 2)
                                out[BQ * 10 + (long)q * 2 + s] = 1.f;
                        }
                    }
                }
            }
        }
        __syncthreads();     // end-of-stage: protects buffers + ACT rewrites
    }
    CP_WAIT0();
}

// ---------------------------------------------------------------------------
// Launch
// ---------------------------------------------------------------------------
extern "C" void kernel_launch(void* const* d_in, const int* in_sizes, int n_in,
                              void* d_out, int out_size)
{
    const float* logits   = (const float*)d_in[0];
    const float* boxes    = (const float*)d_in[1];
    const float* features = (const float*)d_in[2];
    const float* W_p1 = (const float*)d_in[4];
    const float* b_p1 = (const float*)d_in[5];
    const float* ln_g = (const float*)d_in[6];
    const float* ln_b = (const float*)d_in[7];
    const float* W_p2 = (const float*)d_in[8];
    const float* b_p2 = (const float*)d_in[9];
    const float* W_b1 = (const float*)d_in[10];
    const float* b_b1 = (const float*)d_in[11];
    const float* W_b2 = (const float*)d_in[12];
    const float* b_b2 = (const float*)d_in[13];
    const float* W_b3 = (const float*)d_in[14];
    const float* b_b3 = (const float*)d_in[15];
    const float* W_s  = (const float*)d_in[16];
    const float* b_s  = (const float*)d_in[17];
    float* out = (float*)d_out;
    (void)in_sizes; (void)n_in;

    cudaFuncSetAttribute(k_fused, cudaFuncAttributeMaxDynamicSharedMemorySize, FUSED_SMEM);

    k_prep<<<1024 + 750, 256>>>(W_p1, W_p2, W_b1, W_b2, out, out_size);
    k_mask<<<B_ * 2, 1024>>>(logits, boxes);
    k_fused<<<1000, 256, FUSED_SMEM>>>(features, boxes,
                                       b_p1, ln_g, ln_b,
                                       b_p2, W_s, b_s,
                                       b_b1, b_b2,
                                       W_b3, b_b3,
                                       out, out_size);
}

// round 17
// speedup vs baseline: 1.0934x; 1.0934x over previous
#include <cuda_runtime.h>
#include <cuda_bf16.h>
#include <math.h>
#include <stdint.h>

#define B_  64
#define Q_  1000
#define BQ  64000
#define D_  256
#define LOGIT_THR 0.8472978603872034f   // sigmoid(x)>0.7  <=>  x>ln(7/3)

// Weights: single linear array, sel = (plane<<2)|L, 65536 elems each
__device__ __nv_bfloat16 g_w[8 * D_ * D_];
__device__ int           g_idx[BQ];     // q | (cand_bits<<16)
__device__ int           g_ctr[2];      // [0]=cnt, [1]=tile  (memset to 0)

__device__ __forceinline__ uint32_t smem_u32(const void* p) {
    uint32_t r;
    asm("{ .reg .u64 t; cvta.to.shared.u64 t, %1; cvt.u32.u64 %0, t; }" : "=r"(r) : "l"(p));
    return r;
}
__device__ __forceinline__ void cp16(uint32_t dst, const void* src) {
    asm volatile("cp.async.cg.shared.global [%0], [%1], 16;" :: "r"(dst), "l"(src));
}
#define CP_COMMIT()  asm volatile("cp.async.commit_group;")
#define CP_WAIT2()   asm volatile("cp.async.wait_group 2;")
#define CP_WAIT0()   asm volatile("cp.async.wait_group 0;")

#define LDSM4(r, addr) \
    asm volatile("ldmatrix.sync.aligned.m8n8.x4.shared.b16 {%0,%1,%2,%3}, [%4];" \
        : "=r"((r)[0]), "=r"((r)[1]), "=r"((r)[2]), "=r"((r)[3]) : "r"(addr))

#define MMA(d, a, b0, b1) \
    asm volatile("mma.sync.aligned.m16n8k16.row.col.f32.bf16.bf16.f32 " \
        "{%0,%1,%2,%3},{%4,%5,%6,%7},{%8,%9},{%0,%1,%2,%3};" \
        : "+f"((d)[0]), "+f"((d)[1]), "+f"((d)[2]), "+f"((d)[3]) \
        : "r"((a)[0]), "r"((a)[1]), "r"((a)[2]), "r"((a)[3]), "r"(b0), "r"(b1))

__device__ __forceinline__ uint32_t pack2(float a, float b) {
    return (uint32_t)__bfloat16_as_ushort(__float2bfloat16(a))
         | ((uint32_t)__bfloat16_as_ushort(__float2bfloat16(b)) << 16);
}
__device__ __forceinline__ void split2(float a, float b, uint32_t& hw, uint32_t& lw) {
    __nv_bfloat16 h0 = __float2bfloat16(a), h1 = __float2bfloat16(b);
    hw = (uint32_t)__bfloat16_as_ushort(h0) | ((uint32_t)__bfloat16_as_ushort(h1) << 16);
    lw = pack2(a - __bfloat162float(h0), b - __bfloat162float(h1));
}

// ---------------------------------------------------------------------------
// k_maskprep: weight split + output zero + flags/IoU mask + compaction.
//   grid = 128 x 1024. Counters are reset by cudaMemsetAsync before launch.
// ---------------------------------------------------------------------------
__global__ void __launch_bounds__(1024) k_maskprep(
    const float* __restrict__ logits, const float* __restrict__ boxes,
    const float* __restrict__ W0, const float* __restrict__ W1,
    const float* __restrict__ W2, const float* __restrict__ W3,
    float* __restrict__ out, int out_size)
{
    __shared__ float tx1[Q_], ty1[Q_], tx2[Q_], ty2[Q_], tar[Q_];
    __shared__ unsigned char tfl[Q_];
    __shared__ int s_fq[512];
    __shared__ int tn, fn;

    int b = blockIdx.x >> 1, slice = blockIdx.x & 1;
    int t = threadIdx.x;
    int gidx = blockIdx.x * 1024 + t;           // 0..131071

    // ---- prep: weight split (2/thread) ----
#pragma unroll
    for (int e = gidx; e < 4 * D_ * D_; e += 128 * 1024) {
        int wSel = e >> 16, idx = e & 0xFFFF;
        const float* W = (wSel == 0) ? W0 : (wSel == 1) ? W1 : (wSel == 2) ? W2 : W3;
        int k = idx >> 8, n = idx & 255;
        float x = W[idx];
        __nv_bfloat16 h = __float2bfloat16(x);
        g_w[((size_t)wSel << 16) + n * D_ + k] = h;
        g_w[((size_t)(4 + wSel) << 16) + n * D_ + k] =
            __float2bfloat16(x - __bfloat162float(h));
    }
    // ---- prep: output zero ----
    {
        int zn4 = ((out_size >= BQ * 10 + BQ * 2) ? (BQ * 10 + BQ * 2) : (BQ * 10)) / 4;
        float4 z = make_float4(0.f, 0.f, 0.f, 0.f);
        for (int i = gidx; i < zn4; i += 128 * 1024) ((float4*)out)[i] = z;
    }

    // ---- mask ----
    if (t == 0) { tn = 0; fn = 0; }
    __syncthreads();

    if (t < Q_) {
        const float* l = logits + ((long)b * Q_ + t) * 6;
        unsigned f = 0;
        if (l[0] > LOGIT_THR) f |= 1u;
        if (l[4] > LOGIT_THR) f |= 2u;
        if (l[1] > LOGIT_THR) f |= 4u;
        if (l[5] > LOGIT_THR) f |= 8u;
        if (f) {
            const float* bx = boxes + ((long)b * Q_ + t) * 4;
            float cx = bx[0], cy = bx[1], w = bx[2], h = bx[3];
            if (f & 0xCu) {
                int p = atomicAdd(&tn, 1);
                tx1[p] = cx - 0.5f * w; ty1[p] = cy - 0.5f * h;
                tx2[p] = cx + 0.5f * w; ty2[p] = cy + 0.5f * h;
                tar[p] = w * h;
                tfl[p] = (unsigned char)((f >> 2) & 3u);
            }
            if ((f & 3u) && ((t >> 9) == slice)) {
                int p = atomicAdd(&fn, 1);
                s_fq[p] = t | (int)((f & 3u) << 16);
            }
        }
    }
    __syncthreads();

    int nt = tn, nf = fn;
    int sub = t & 3;

    for (int e = t >> 2; e < nf; e += 256) {
        int v = s_fq[e];
        int q = v & 0xFFFF;
        unsigned need = (unsigned)(v >> 16) & 3u;
        const float4 bx = *(const float4*)(boxes + ((long)b * Q_ + q) * 4);
        float x1 = bx.x - 0.5f * bx.z, y1 = bx.y - 0.5f * bx.w;
        float x2 = bx.x + 0.5f * bx.z, y2 = bx.y + 0.5f * bx.w;
        float ar = bx.z * bx.w;
        unsigned has = 0;
        for (int j = sub; j < nt; j += 4) {
            float xl = fmaxf(x1, tx1[j]), yt = fmaxf(y1, ty1[j]);
            float xr = fminf(x2, tx2[j]), yb = fminf(y2, ty2[j]);
            float inter = fmaxf(xr - xl, 0.f) * fmaxf(yb - yt, 0.f);
            float uni = ar + tar[j] - inter;
            if (inter > 0.5f * uni) {
                has |= (unsigned)tfl[j];
                if ((has & need) == need) break;
            }
        }
        has |= __shfl_xor_sync(0xffffffffu, has, 1);
        has |= __shfl_xor_sync(0xffffffffu, has, 2);
        if (sub == 0) {
            unsigned cm = need & ~has;
            if (cm) {
                int pos = atomicAdd(&g_ctr[0], 1);
                g_idx[pos] = (b * Q_ + q) | ((int)cm << 16);
            }
        }
    }
}

// ---------------------------------------------------------------------------
// k_fused: R15 engine — persistent CTAs (296), dynamic tile queue, 32-row
//          tiles, 4 B-buffers, depth-3 issue (wait_group 2), 1 barrier/stage.
// ---------------------------------------------------------------------------
#define S_ACTH 0
#define S_ACTL 16384
#define S_B    32768
#define S_B4A  98304
#define S_LNG  102400
#define S_LNB  103424
#define S_WS   104448
#define S_WB3  105472
#define S_PS   109568
#define S_PS2  110080
#define S_DP   110592
#define S_SC   112640
#define S_QI   112768
#define FUSED_SMEM 112896

__global__ void __launch_bounds__(256, 2) k_fused(
    const float* __restrict__ feat, const float* __restrict__ boxes,
    const float* __restrict__ b1, const float* __restrict__ lng, const float* __restrict__ lnb,
    const float* __restrict__ b2, const float* __restrict__ ws, const float* __restrict__ bs,
    const float* __restrict__ b3, const float* __restrict__ b4,
    const float* __restrict__ wb3, const float* __restrict__ bb3,
    float* __restrict__ out, int out_size)
{
    __shared__ int s_tile;
    int cnt = g_ctr[0];
    int numTiles = (cnt + 31) >> 5;

    extern __shared__ __align__(1024) char sm[];
    uint32_t base = smem_u32(sm);
    int tid = threadIdx.x, wid = tid >> 5, lane = tid & 31;
    int wm = wid & 1, wn = wid >> 1;
    int qg = lane >> 2, qt = lane & 3;

    int n0 = tid >> 2, sg = tid & 3;
    uint32_t sdst0 = base + S_B + n0 * 64 + ((sg * 16) ^ ((n0 & 6) << 3));
    uint32_t goff0 = (uint32_t)n0 * D_ + sg * 8;

    int rl = lane & 15;
    int cb0 = (lane >> 4) << 4;
    int rowA = wm * 16 + rl;
    uint32_t swr = (uint32_t)((rowA & 7) << 4);
    uint32_t aOff[2][2], bOff[4][2];
#pragma unroll
    for (int c = 0; c < 2; c++)
#pragma unroll
        for (int k = 0; k < 2; k++)
            aOff[c][k] = (uint32_t)(rowA * 128) + (((uint32_t)(c * 64 + cb0 + k * 32)) ^ swr);
#pragma unroll
    for (int j4 = 0; j4 < 4; j4++) {
        int n = wn * 64 + j4 * 16 + rl;
#pragma unroll
        for (int k = 0; k < 2; k++)
            bOff[j4][k] = (uint32_t)(n * 64) + (((uint32_t)(cb0 + k * 32)) ^ ((uint32_t)((n & 6) << 3)));
    }

    {
        float* s_b4 = (float*)(sm + S_B4A);
        s_b4[0 * 256 + tid] = __ldg(b1 + tid);
        s_b4[1 * 256 + tid] = __ldg(b2 + tid);
        s_b4[2 * 256 + tid] = __ldg(b3 + tid);
        s_b4[3 * 256 + tid] = __ldg(b4 + tid);
        ((float*)(sm + S_LNG))[tid] = __ldg(lng + tid);
        ((float*)(sm + S_LNB))[tid] = __ldg(lnb + tid);
        ((float*)(sm + S_WS))[tid]  = __ldg(ws + tid);
        ((float4*)(sm + S_WB3))[tid] = __ldg((const float4*)wb3 + tid);
    }

    float* s_ps  = (float*)(sm + S_PS);
    float* s_ps2 = (float*)(sm + S_PS2);
    float* s_dp  = (float*)(sm + S_DP);
    float* s_sc  = (float*)(sm + S_SC);

    float acc[8][4];
    float mu[2], rs[2], scp[2], dp[2][4];

    while (true) {
        if (tid == 0) s_tile = atomicAdd(&g_ctr[1], 1);
        __syncthreads();
        int tile = s_tile;
        __syncthreads();
        if (tile >= numTiles) break;
        int blockRow = tile << 5;

        if (tid < 32) {
            int gr = blockRow + tid;
            ((int*)(sm + S_QI))[tid] = (gr < cnt) ? g_idx[gr] : -1;
        }
        for (int it = tid; it < 1024; it += 256) {
            int row = it >> 5, grp = it & 31;
            uint4 hi = make_uint4(0, 0, 0, 0), lo = make_uint4(0, 0, 0, 0);
            int gr = blockRow + row;
            if (gr < cnt) {
                int q = g_idx[gr] & 0xFFFF;
                const float4* f4 = (const float4*)feat + (size_t)q * 64 + grp * 2;
                float4 fa = __ldg(f4), fb = __ldg(f4 + 1);
                split2(fa.x, fa.y, hi.x, lo.x);
                split2(fa.z, fa.w, hi.y, lo.y);
                split2(fb.x, fb.y, hi.z, lo.z);
                split2(fb.z, fb.w, hi.w, lo.w);
            }
            int c8 = grp * 8;
            int blk = c8 >> 6;
            uint32_t sw = blk * 4096 + row * 128 + (((c8 & 63) * 2) ^ ((row & 7) << 4));
            *(uint4*)(sm + S_ACTH + sw) = hi;
            *(uint4*)(sm + S_ACTL + sw) = lo;
        }

#pragma unroll
        for (int t0 = 0; t0 < 3; t0++) {
            int sel = (t0 & 1) << 2;
            const __nv_bfloat16* w = g_w + ((size_t)sel << 16) + ((t0 >> 1) * 32) + goff0;
            uint32_t dst = sdst0 + ((uint32_t)t0 << 14);
            cp16(dst, w); cp16(dst + 4096, w + 16384);
            cp16(dst + 8192, w + 32768); cp16(dst + 12288, w + 49152);
            CP_COMMIT();
        }

#pragma unroll 1
        for (int t = 0; t < 64; t++) {
            int L = t >> 4, rem = t & 15, c2 = rem >> 1, plane = rem & 1;

            CP_WAIT2();
            __syncthreads();

            {
                int t3 = t + 3;
                if (t3 < 64) {
                    int sel = ((t3 & 1) << 2) | (t3 >> 4);
                    const __nv_bfloat16* w = g_w + ((size_t)sel << 16)
                                           + (((t3 & 15) >> 1) * 32) + goff0;
                    uint32_t dst = sdst0 + ((uint32_t)(t3 & 3) << 14);
                    cp16(dst, w); cp16(dst + 4096, w + 16384);
                    cp16(dst + 8192, w + 32768); cp16(dst + 12288, w + 49152);
                }
                CP_COMMIT();
            }

            if (rem == 0) {
#pragma unroll
                for (int j = 0; j < 8; j++)
#pragma unroll
                    for (int r = 0; r < 4; r++) acc[j][r] = 0.f;
            }

            uint32_t bufb = base + S_B + ((uint32_t)(t & 3) << 14);
            uint32_t ab = base + S_ACTH + ((uint32_t)(c2 >> 1) << 12);
            int cc = c2 & 1;
#pragma unroll
            for (int ks = 0; ks < 2; ks++) {
                uint32_t Bf[4][4], Af[4];
                LDSM4(Bf[0], bufb + bOff[0][ks]);
                LDSM4(Bf[1], bufb + bOff[1][ks]);
                LDSM4(Bf[2], bufb + bOff[2][ks]);
                LDSM4(Bf[3], bufb + bOff[3][ks]);
                LDSM4(Af, ab + aOff[cc][ks]);
#pragma unroll
                for (int j = 0; j < 8; j++) {
                    int j4 = j >> 1, sel = j & 1;
                    MMA(acc[j], Af, Bf[j4][sel], Bf[j4][sel + 2]);
                }
                if (plane == 0) {
                    LDSM4(Af, ab + 16384 + aOff[cc][ks]);
#pragma unroll
                    for (int j = 0; j < 8; j++) {
                        int j4 = j >> 1, sel = j & 1;
                        MMA(acc[j], Af, Bf[j4][sel], Bf[j4][sel + 2]);
                    }
                }
            }

            if (rem == 15) {
                const float* s_bias = (const float*)(sm + S_B4A) + L * 256;
                if (L == 0) {
                    const float* g1 = (const float*)(sm + S_LNG);
                    const float* g2 = (const float*)(sm + S_LNB);
                    float ps[2] = {0, 0}, ps2[2] = {0, 0};
#pragma unroll
                    for (int j = 0; j < 8; j++) {
                        int c0 = wn * 64 + j * 8 + 2 * qt;
                        float v00 = acc[j][0] + s_bias[c0], v01 = acc[j][1] + s_bias[c0 + 1];
                        float v10 = acc[j][2] + s_bias[c0], v11 = acc[j][3] + s_bias[c0 + 1];
                        ps[0] += v00 + v01; ps2[0] += v00 * v00 + v01 * v01;
                        ps[1] += v10 + v11; ps2[1] += v10 * v10 + v11 * v11;
                    }
#pragma unroll
                    for (int h = 0; h < 2; h++) {
                        ps[h]  += __shfl_xor_sync(0xffffffffu, ps[h], 1);
                        ps[h]  += __shfl_xor_sync(0xffffffffu, ps[h], 2);
                        ps2[h] += __shfl_xor_sync(0xffffffffu, ps2[h], 1);
                        ps2[h] += __shfl_xor_sync(0xffffffffu, ps2[h], 2);
                        if (qt == 0) {
                            int r = wm * 16 + qg + h * 8;
                            s_ps[r * 4 + wn] = ps[h];
                            s_ps2[r * 4 + wn] = ps2[h];
                        }
                    }
                    __syncthreads();
#pragma unroll
                    for (int h = 0; h < 2; h++) {
                        int r = wm * 16 + qg + h * 8;
                        float S = s_ps[r * 4] + s_ps[r * 4 + 1] + s_ps[r * 4 + 2] + s_ps[r * 4 + 3];
                        float S2 = s_ps2[r * 4] + s_ps2[r * 4 + 1] + s_ps2[r * 4 + 2] + s_ps2[r * 4 + 3];
                        float m = S * (1.f / 256.f);
                        mu[h] = m;
                        rs[h] = rsqrtf(S2 * (1.f / 256.f) - m * m + 1e-5f);
                    }
#pragma unroll
                    for (int j = 0; j < 8; j++) {
                        int c0 = wn * 64 + j * 8 + 2 * qt;
                        int byte = (c0 & 63) * 2, blk = c0 >> 6;
#pragma unroll
                        for (int h = 0; h < 2; h++) {
                            int r = wm * 16 + qg + h * 8;
                            float v0 = fmaxf(((acc[j][2 * h]     + s_bias[c0])     - mu[h]) * rs[h] * g1[c0]     + g2[c0],     0.f);
                            float v1 = fmaxf(((acc[j][2 * h + 1] + s_bias[c0 + 1]) - mu[h]) * rs[h] * g1[c0 + 1] + g2[c0 + 1], 0.f);
                            uint32_t hw, lw; split2(v0, v1, hw, lw);
                            uint32_t a = blk * 4096 + r * 128 + ((byte & ~15) ^ ((r & 7) << 4)) + (byte & 15);
                            *(uint32_t*)(sm + S_ACTH + a) = hw;
                            *(uint32_t*)(sm + S_ACTL + a) = lw;
                        }
                    }
                } else if (L == 1) {
                    const float* wsv = (const float*)(sm + S_WS);
                    scp[0] = 0.f; scp[1] = 0.f;
#pragma unroll
                    for (int j = 0; j < 8; j++) {
                        int c0 = wn * 64 + j * 8 + 2 * qt;
                        int byte = (c0 & 63) * 2, blk = c0 >> 6;
#pragma unroll
                        for (int h = 0; h < 2; h++) {
                            int r = wm * 16 + qg + h * 8;
                            float v0 = acc[j][2 * h]     + s_bias[c0];
                            float v1 = acc[j][2 * h + 1] + s_bias[c0 + 1];
                            scp[h] += v0 * wsv[c0] + v1 * wsv[c0 + 1];
                            uint32_t hw, lw; split2(v0, v1, hw, lw);
                            uint32_t a = blk * 4096 + r * 128 + ((byte & ~15) ^ ((r & 7) << 4)) + (byte & 15);
                            *(uint32_t*)(sm + S_ACTH + a) = hw;
                            *(uint32_t*)(sm + S_ACTL + a) = lw;
                        }
                    }
#pragma unroll
                    for (int h = 0; h < 2; h++) {
                        scp[h] += __shfl_xor_sync(0xffffffffu, scp[h], 1);
                        scp[h] += __shfl_xor_sync(0xffffffffu, scp[h], 2);
                        if (qt == 0) {
                            int r = wm * 16 + qg + h * 8;
                            s_ps[r * 4 + wn] = scp[h];
                        }
                    }
                    __syncthreads();
                    if (tid < 32)
                        s_sc[tid] = s_ps[tid * 4] + s_ps[tid * 4 + 1]
                                  + s_ps[tid * 4 + 2] + s_ps[tid * 4 + 3] + __ldg(bs);
                } else if (L == 2) {
#pragma unroll
                    for (int j = 0; j < 8; j++) {
                        int c0 = wn * 64 + j * 8 + 2 * qt;
                        int byte = (c0 & 63) * 2, blk = c0 >> 6;
#pragma unroll
                        for (int h = 0; h < 2; h++) {
                            int r = wm * 16 + qg + h * 8;
                            float v0 = fmaxf(acc[j][2 * h]     + s_bias[c0],     0.f);
                            float v1 = fmaxf(acc[j][2 * h + 1] + s_bias[c0 + 1], 0.f);
                            uint32_t hw, lw; split2(v0, v1, hw, lw);
                            uint32_t a = blk * 4096 + r * 128 + ((byte & ~15) ^ ((r & 7) << 4)) + (byte & 15);
                            *(uint32_t*)(sm + S_ACTH + a) = hw;
                            *(uint32_t*)(sm + S_ACTL + a) = lw;
                        }
                    }
                } else {
                    const float* w3t = (const float*)(sm + S_WB3);
#pragma unroll
                    for (int h = 0; h < 2; h++)
#pragma unroll
                        for (int k = 0; k < 4; k++) dp[h][k] = 0.f;
#pragma unroll
                    for (int j = 0; j < 8; j++) {
                        int c0 = wn * 64 + j * 8 + 2 * qt;
#pragma unroll
                        for (int h = 0; h < 2; h++) {
                            float v0 = fmaxf(acc[j][2 * h]     + s_bias[c0],     0.f);
                            float vv = fmaxf(acc[j][2 * h + 1] + s_bias[c0 + 1], 0.f);
                            const float* w0 = &w3t[c0 * 4];
#pragma unroll
                            for (int k = 0; k < 4; k++)
                                dp[h][k] += v0 * w0[k] + vv * w0[4 + k];
                        }
                    }
#pragma unroll
                    for (int h = 0; h < 2; h++)
#pragma unroll
                        for (int k = 0; k < 4; k++) {
                            dp[h][k] += __shfl_xor_sync(0xffffffffu, dp[h][k], 1);
                            dp[h][k] += __shfl_xor_sync(0xffffffffu, dp[h][k], 2);
                            if (qt == 0) {
                                int r = wm * 16 + qg + h * 8;
                                s_dp[r * 16 + wn * 4 + k] = dp[h][k];
                            }
                        }
                    __syncthreads();
                    if (tid < 32) {
                        int v = ((int*)(sm + S_QI))[tid];
                        if (v >= 0) {
                            float d[4];
#pragma unroll
                            for (int k = 0; k < 4; k++)
                                d[k] = s_dp[tid * 16 + k] + s_dp[tid * 16 + 4 + k]
                                     + s_dp[tid * 16 + 8 + k] + s_dp[tid * 16 + 12 + k]
                                     + __ldg(bb3 + k);
                            float scv = s_sc[tid];
                            int q = v & 0xFFFF;
                            unsigned cm = (unsigned)(v >> 16);
                            float4 bx = *(const float4*)(boxes + (long)q * 4);
                            float cx = bx.x, cy = bx.y, w = bx.z, hh = bx.w;
                            float ny = cy + 0.5f * hh, nw = w * 0.8f, nh = hh * 0.8f;
                            float lb[4]  = {cx,            ny, nw, nh};
                            float rbx[4] = {cx + 0.1f * w, ny, nw, nh};
#pragma unroll
                            for (int s = 0; s < 2; s++) {
                                if (!((cm >> s) & 1u)) continue;
                                const float* cb = s ? rbx : lb;
                                long basei = ((long)q * 2 + s) * 5;
#pragma unroll
                                for (int c = 0; c < 4; c++) {
                                    float x = fminf(fmaxf(cb[c], 0.f), 1.f);
                                    float inv = logf(fmaxf(x, 1e-5f) / fmaxf(1.f - x, 1e-5f));
                                    out[basei + c] = 1.f / (1.f + expf(-(d[c] + inv)));
                                }
                                out[basei + 4] = scv;
                                if (out_size >= BQ * 10 + BQ * 2)
                                    out[BQ * 10 + (long)q * 2 + s] = 1.f;
                            }
                        }
                    }
                }
            }
        }
        __syncthreads();
    }
    CP_WAIT0();
}

// ---------------------------------------------------------------------------
// Launch: memset(counters) + 2 kernels
// ---------------------------------------------------------------------------
extern "C" void kernel_launch(void* const* d_in, const int* in_sizes, int n_in,
                              void* d_out, int out_size)
{
    const float* logits   = (const float*)d_in[0];
    const float* boxes    = (const float*)d_in[1];
    const float* features = (const float*)d_in[2];
    const float* W_p1 = (const float*)d_in[4];
    const float* b_p1 = (const float*)d_in[5];
    const float* ln_g = (const float*)d_in[6];
    const float* ln_b = (const float*)d_in[7];
    const float* W_p2 = (const float*)d_in[8];
    const float* b_p2 = (const float*)d_in[9];
    const float* W_b1 = (const float*)d_in[10];
    const float* b_b1 = (const float*)d_in[11];
    const float* W_b2 = (const float*)d_in[12];
    const float* b_b2 = (const float*)d_in[13];
    const float* W_b3 = (const float*)d_in[14];
    const float* b_b3 = (const float*)d_in[15];
    const float* W_s  = (const float*)d_in[16];
    const float* b_s  = (const float*)d_in[17];
    float* out = (float*)d_out;
    (void)in_sizes; (void)n_in;

    cudaFuncSetAttribute(k_fused, cudaFuncAttributeMaxDynamicSharedMemorySize, FUSED_SMEM);

    void* ctrAddr = nullptr;
    cudaGetSymbolAddress(&ctrAddr, g_ctr);
    cudaMemsetAsync(ctrAddr, 0, 2 * sizeof(int));

    k_maskprep<<<B_ * 2, 1024>>>(logits, boxes, W_p1, W_p2, W_b1, W_b2, out, out_size);
    k_fused<<<296, 256, FUSED_SMEM>>>(features, boxes,
                                      b_p1, ln_g, ln_b,
                                      b_p2, W_s, b_s,
                                      b_b1, b_b2,
                                      W_b3, b_b3,
                                      out, out_size);
}